// round 2
// baseline (speedup 1.0000x reference)
#include <cuda_runtime.h>
#include <cuda_bf16.h>
#include <cstdint>

// ---------------------------------------------------------------------------
// Problem constants
// ---------------------------------------------------------------------------
#define NROWS 2048
#define NFEAT 128
#define TILE  128

// ---------------------------------------------------------------------------
// Device scratch (no allocation allowed)
// ---------------------------------------------------------------------------
__device__ __nv_bfloat16 g_Xb[NROWS * NFEAT];   // bf16-quantized X
__device__ float g_norm[NROWS];                 // row norms of quantized X
__device__ float g_s_part[64][NFEAT];           // per-block feature-sum partials
__device__ float g_sumn_part[64];               // per-block sum-of-norms partials
__device__ float g_inv2s;                       // 1 / (2 sigma^2)

// ---------------------------------------------------------------------------
// Helpers
// ---------------------------------------------------------------------------
__device__ __forceinline__ uint32_t smem_to_u32(const void* p) {
    uint32_t a;
    asm("{ .reg .u64 t; cvta.to.shared.u64 t, %1; cvt.u32.u64 %0, t; }" : "=r"(a) : "l"(p));
    return a;
}

__device__ __forceinline__ void ldmatrix_x4(uint32_t& r0, uint32_t& r1,
                                            uint32_t& r2, uint32_t& r3, uint32_t addr) {
    asm volatile("ldmatrix.sync.aligned.m8n8.x4.shared.b16 {%0,%1,%2,%3}, [%4];"
                 : "=r"(r0), "=r"(r1), "=r"(r2), "=r"(r3) : "r"(addr));
}

__device__ __forceinline__ void mma_16816(float* d, const uint32_t* a, const uint32_t* b) {
    asm volatile(
        "mma.sync.aligned.m16n8k16.row.col.f32.bf16.bf16.f32 "
        "{%0,%1,%2,%3}, {%4,%5,%6,%7}, {%8,%9}, {%0,%1,%2,%3};"
        : "+f"(d[0]), "+f"(d[1]), "+f"(d[2]), "+f"(d[3])
        : "r"(a[0]), "r"(a[1]), "r"(a[2]), "r"(a[3]), "r"(b[0]), "r"(b[1]));
}

// ---------------------------------------------------------------------------
// Kernel 1: quantize to bf16, row norms, feature-sum partials (deterministic)
// grid 64, block 256: block handles 32 rows; warp w handles rows rb+w*4 .. +3
// ---------------------------------------------------------------------------
__global__ void __launch_bounds__(256) prep_kernel(const float* __restrict__ X) {
    int b   = blockIdx.x;
    int tid = threadIdx.x;
    int wid = tid >> 5;
    int lid = tid & 31;
    int rb  = b * 32;

    __shared__ float ss[8][NFEAT];
    __shared__ float sn[8];

    float s0 = 0.f, s1 = 0.f, s2 = 0.f, s3 = 0.f;
    float wn = 0.f;

    #pragma unroll
    for (int r = 0; r < 4; r++) {
        int row = rb + wid * 4 + r;
        float4 v = reinterpret_cast<const float4*>(X + (size_t)row * NFEAT)[lid];
        __nv_bfloat16 b0 = __float2bfloat16(v.x);
        __nv_bfloat16 b1 = __float2bfloat16(v.y);
        __nv_bfloat16 b2 = __float2bfloat16(v.z);
        __nv_bfloat16 b3 = __float2bfloat16(v.w);
        __nv_bfloat162* dst =
            reinterpret_cast<__nv_bfloat162*>(g_Xb + (size_t)row * NFEAT) + lid * 2;
        dst[0] = __nv_bfloat162(b0, b1);
        dst[1] = __nv_bfloat162(b2, b3);
        // use quantized values downstream (diag becomes exactly 0 -> out=1)
        float fx = __bfloat162float(b0), fy = __bfloat162float(b1);
        float fz = __bfloat162float(b2), fw = __bfloat162float(b3);
        float sq = fx * fx + fy * fy + fz * fz + fw * fw;
        #pragma unroll
        for (int o = 16; o > 0; o >>= 1) sq += __shfl_xor_sync(0xFFFFFFFFu, sq, o);
        if (lid == 0) { g_norm[row] = sq; wn += sq; }
        s0 += fx; s1 += fy; s2 += fz; s3 += fw;
    }
    ss[wid][lid * 4 + 0] = s0;
    ss[wid][lid * 4 + 1] = s1;
    ss[wid][lid * 4 + 2] = s2;
    ss[wid][lid * 4 + 3] = s3;
    if (lid == 0) sn[wid] = wn;
    __syncthreads();
    if (tid < NFEAT) {
        float t = 0.f;
        #pragma unroll
        for (int w = 0; w < 8; w++) t += ss[w][tid];
        g_s_part[b][tid] = t;
    }
    if (tid == 0) {
        float t = 0.f;
        #pragma unroll
        for (int w = 0; w < 8; w++) t += sn[w];
        g_sumn_part[b] = t;
    }
}

// ---------------------------------------------------------------------------
// Kernel 2: finalize sigma.  sigma^2 = (2N*sum_n - 2*|s|^2) / N^2   (ALPHA=1)
// ---------------------------------------------------------------------------
__global__ void __launch_bounds__(128) finalize_kernel() {
    int tid = threadIdx.x;
    int wid = tid >> 5, lid = tid & 31;
    __shared__ float red[4];

    float sf = 0.f;
    for (int b = 0; b < 64; b++) sf += g_s_part[b][tid];
    float v = sf * sf;
    #pragma unroll
    for (int o = 16; o > 0; o >>= 1) v += __shfl_xor_sync(0xFFFFFFFFu, v, o);
    if (lid == 0) red[wid] = v;
    __syncthreads();
    if (tid == 0) {
        float S2 = red[0] + red[1] + red[2] + red[3];
        float sumn = 0.f;
        for (int b = 0; b < 64; b++) sumn += g_sumn_part[b];
        float Nf = (float)NROWS;
        float sigma2 = (2.f * Nf * sumn - 2.f * S2) / (Nf * Nf);
        g_inv2s = 1.f / (2.f * sigma2);
    }
}

// ---------------------------------------------------------------------------
// Kernel 3: main. grid (16,16), 256 threads (8 warps).
// CTA computes a 128x128 output tile via ldmatrix + mma.sync bf16 (HMMA).
// Smem tiles: A,B = 128 rows x 128 bf16 (256B/row, 16B chunks, chunk-XOR swizzle).
// Warp (wid%4, wid/4) computes rows wm..wm+31, cols wn..wn+63.
// Epilogue: exp((2*dot - ni - nj) * inv2s) from register accumulators.
// ---------------------------------------------------------------------------
#define OFF_NJS 0
#define OFF_A   1024
#define OFF_B   (1024 + 32768)
#define SMEM_TOTAL (OFF_B + 32768)

__global__ void __launch_bounds__(256) gauss_main_kernel(float* __restrict__ out) {
    extern __shared__ char smem[];
    uint32_t sb = smem_to_u32(smem);
    int tid = threadIdx.x;
    int wid = tid >> 5;
    int lid = tid & 31;
    int bj  = blockIdx.x;
    int bi  = blockIdx.y;

    // nj tile into smem
    if (tid < TILE)
        reinterpret_cast<float*>(smem + OFF_NJS)[tid] = g_norm[bj * TILE + tid];

    // ---- load A/B tiles into swizzled smem ----
    // row r, 16B-chunk c (0..15): smem offset = r*256 + (c ^ (r&7))*16
    const uint4* A4 = reinterpret_cast<const uint4*>(g_Xb + (size_t)bi * TILE * NFEAT);
    const uint4* B4 = reinterpret_cast<const uint4*>(g_Xb + (size_t)bj * TILE * NFEAT);
    #pragma unroll
    for (int idx = tid; idx < 2048; idx += 256) {
        int row = idx >> 4;
        int c   = idx & 15;
        uint32_t off = (uint32_t)row * 256u + (uint32_t)(c ^ (row & 7)) * 16u;
        *reinterpret_cast<uint4*>(smem + OFF_A + off) = A4[idx];
        *reinterpret_cast<uint4*>(smem + OFF_B + off) = B4[idx];
    }
    __syncthreads();

    // ---- per-warp MMA ----
    int wm = (wid & 3) * 32;   // row base within tile
    int wn = (wid >> 2) * 64;  // col base within tile

    float d[2][8][4];
    #pragma unroll
    for (int mt = 0; mt < 2; mt++)
        #pragma unroll
        for (int nt = 0; nt < 8; nt++)
            #pragma unroll
            for (int e = 0; e < 4; e++) d[mt][nt][e] = 0.f;

    // A ldmatrix lane addressing (m16n8k16 A frag, x4):
    //   lane row = wm + mt*16 + (lane & 15);  chunk = 2*kc + (lane>>4)
    uint32_t a_row  = (uint32_t)(wm + (lid & 15));
    uint32_t a_cbit = (uint32_t)(lid >> 4);
    uint32_t a_rl   = a_row & 7;
    uint32_t a_base0 = sb + OFF_A + a_row * 256u;
    uint32_t a_base1 = a_base0 + 16u * 256u;

    // B ldmatrix lane addressing (two n-tiles per x4):
    //   lane row = wn + p*16 + (lane & 7) + ((lane & 16) >> 1); chunk = 2*kc + ((lane>>3)&1)
    uint32_t b_row  = (uint32_t)(wn + (lid & 7) + ((lid & 16) >> 1));
    uint32_t b_cbit = (uint32_t)((lid >> 3) & 1);
    uint32_t b_rl   = b_row & 7;
    uint32_t b_base = sb + OFF_B + b_row * 256u;

    #pragma unroll
    for (int kc = 0; kc < 8; kc++) {
        uint32_t a[2][4];
        {
            uint32_t sc = ((uint32_t)(2 * kc) + a_cbit) ^ a_rl;
            ldmatrix_x4(a[0][0], a[0][1], a[0][2], a[0][3], a_base0 + (sc << 4));
            ldmatrix_x4(a[1][0], a[1][1], a[1][2], a[1][3], a_base1 + (sc << 4));
        }
        uint32_t b[8][2];
        #pragma unroll
        for (int p = 0; p < 4; p++) {
            uint32_t sc = ((uint32_t)(2 * kc) + b_cbit) ^ b_rl;
            uint32_t addr = b_base + (uint32_t)p * (16u * 256u) + (sc << 4);
            ldmatrix_x4(b[2 * p][0], b[2 * p][1], b[2 * p + 1][0], b[2 * p + 1][1], addr);
        }
        #pragma unroll
        for (int mt = 0; mt < 2; mt++)
            #pragma unroll
            for (int nt = 0; nt < 8; nt++)
                mma_16816(d[mt][nt], a[mt], b[nt]);
    }

    // ---- epilogue: exp((2*dot - ni - nj) * inv2s), stores from registers ----
    float inv2s = g_inv2s;
    float scale = 2.f * inv2s;
    const float* njs = reinterpret_cast<const float*>(smem + OFF_NJS);
    int quad = lid >> 2;        // row within 8
    int qt   = lid & 3;         // col pair selector

    #pragma unroll
    for (int mt = 0; mt < 2; mt++) {
        #pragma unroll
        for (int half = 0; half < 2; half++) {
            int r = wm + mt * 16 + quad + half * 8;
            float ni = g_norm[bi * TILE + r];
            float* orow = out + (size_t)(bi * TILE + r) * NROWS + (size_t)bj * TILE + wn;
            #pragma unroll
            for (int nt = 0; nt < 8; nt++) {
                int col = nt * 8 + qt * 2;
                float nj0 = njs[wn + col];
                float nj1 = njs[wn + col + 1];
                float dot0 = d[mt][nt][half * 2 + 0];
                float dot1 = d[mt][nt][half * 2 + 1];
                float e0 = fmaf(dot0, scale, -(ni + nj0) * inv2s);
                float e1 = fmaf(dot1, scale, -(ni + nj1) * inv2s);
                float2 o = make_float2(__expf(e0), __expf(e1));
                *reinterpret_cast<float2*>(orow + col) = o;
            }
        }
    }
}

// ---------------------------------------------------------------------------
// Launch
// ---------------------------------------------------------------------------
extern "C" void kernel_launch(void* const* d_in, const int* in_sizes, int n_in,
                              void* d_out, int out_size) {
    const float* X = (const float*)d_in[0];
    float* out = (float*)d_out;
    (void)in_sizes; (void)n_in; (void)out_size;

    cudaFuncSetAttribute(gauss_main_kernel,
                         cudaFuncAttributeMaxDynamicSharedMemorySize, SMEM_TOTAL);

    prep_kernel<<<64, 256>>>(X);
    finalize_kernel<<<1, 128>>>();
    gauss_main_kernel<<<dim3(16, 16), 256, SMEM_TOTAL>>>(out);
}